// round 7
// baseline (speedup 1.0000x reference)
#include <cuda_runtime.h>

#define NTYPES 20
#define LMAXC  13
#define DV     64
#define NRES_MAX 2048
#define B_MAX    16

__constant__ int c_res_len[NTYPES] = {3,4,5,5,6,6,6,7,7,7,7,7,8,8,8,9,10,10,11,13};

__device__ int g_starts[NRES_MAX];     // atom start per residue
__device__ int g_rowstart[NRES_MAX];   // first output-row per residue

// ---------------------------------------------------------------------------
// Setup: two warp-shuffle scans only.
// ---------------------------------------------------------------------------
__device__ __forceinline__ int block_excl_scan_pair(int my, int tid, int* wsum) {
    const int lane = tid & 31, wid = tid >> 5;
    int s = my;
#pragma unroll
    for (int o = 1; o < 32; o <<= 1) {
        int n = __shfl_up_sync(~0u, s, o);
        if (lane >= o) s += n;
    }
    if (lane == 31) wsum[wid] = s;
    __syncthreads();
    if (wid == 0) {
        int t = wsum[lane];
#pragma unroll
        for (int o = 1; o < 32; o <<= 1) {
            int n = __shfl_up_sync(~0u, t, o);
            if (lane >= o) t += n;
        }
        wsum[lane] = t;
    }
    __syncthreads();
    int base = ((wid > 0) ? wsum[wid - 1] : 0) + (s - my);
    __syncthreads();
    return base;
}

__global__ void setup_kernel(const int* __restrict__ seq, int nres) {
    __shared__ int wsum[32];
    __shared__ int slen[NTYPES];
    const int tid = threadIdx.x;
    if (tid < NTYPES) slen[tid] = c_res_len[tid];
    __syncthreads();

    const int j0 = 2 * tid, j1 = 2 * tid + 1;
    const int l0 = (j0 < nres) ? slen[seq[j0]] : 0;
    const int l1 = (j1 < nres) ? slen[seq[j1]] : 0;

    const int base = block_excl_scan_pair(l0 + l1, tid, wsum);
    if (j0 < nres) g_starts[j0] = base;
    if (j1 < nres) g_starts[j1] = base + l0;

    const int r0 = (j0 < nres) ? l0 + 1 : 0;
    const int r1 = (j1 < nres) ? l1 + 1 : 0;
    const int rbase = block_excl_scan_pair(r0 + r1, tid, wsum);
    if (j0 < nres) g_rowstart[j0] = rbase;
    if (j1 < nres) g_rowstart[j1] = rbase + r0;
}

// ---------------------------------------------------------------------------
// Main kernel helpers
// ---------------------------------------------------------------------------
#define PACK2(dst, a, b) \
    asm("mov.b64 %0, {%1, %2};" : "=l"(dst) : "r"(__float_as_uint(a)), "r"(__float_as_uint(b)))
#define FMA2(acc, x, y) \
    asm("fma.rn.f32x2 %0, %1, %2, %3;" : "=l"(acc) : "l"(x), "l"(y), "l"(acc))
#define ADD2(dst, x, y) \
    asm("add.rn.f32x2 %0, %1, %2;" : "=l"(dst) : "l"(x), "l"(y))
#define UNPACK2(lo, hi, src) \
    asm("mov.b64 {%0, %1}, %2;" : "=r"(lo), "=r"(hi) : "l"(src))
#define LDS_V2U64(x, y, addr) \
    asm volatile("ld.shared.v2.u64 {%0, %1}, [%2];" : "=l"(x), "=l"(y) : "r"(addr))

__device__ __forceinline__ unsigned smem_u32(const void* p) {
    unsigned r;
    asm("{ .reg .u64 t; cvta.to.shared.u64 t, %1; cvt.u32.u64 %0, t; }" : "=r"(r) : "l"(p));
    return r;
}

// Each thread computes 3 output scalars per batch:
//   u_c = sum_l W[ch_c][l] * diff_c[l]   (c = component 0,1,2)
// and stores them to dense positions  base + 32k + lam  (k = 0,1,2).
template <int L>
__device__ __forceinline__ void batch_loop(
    int B, bool active, unsigned curDiff,
    const float* __restrict__ swRow,      // smem weights for this slot: [64][13]
    int ch0, int ch1, int ch2,            // channel per component
    int ck0, int ck1, int ck2,            // component stored by slot k
    float* __restrict__ op, long ostride) // op -> base + 96*wis + lam
{
    // register-fill + pack weights: (w_c0, w_c1) as f32x2, w_c2 scalar
    unsigned long long ww01[L];
    float w2[L];
#pragma unroll
    for (int l = 0; l < L; ++l) {
        const float w0 = swRow[ch0 * LMAXC + l];
        const float w1 = swRow[ch1 * LMAXC + l];
        w2[l] = swRow[ch2 * LMAXC + l];
        PACK2(ww01[l], w0, w1);
    }

    const bool s00 = (ck0 == 0), s01 = (ck0 == 1);
    const bool s10 = (ck1 == 0), s11 = (ck1 == 1);
    const bool s20 = (ck2 == 0), s21 = (ck2 == 1);

#pragma unroll 2
    for (int b = 0; b < B; ++b) {
        unsigned long long aA = 0ull, aB = 0ull;
        float cA = 0.0f, cB = 0.0f;
#pragma unroll
        for (int l = 0; l < L; ++l) {
            unsigned long long d01, d2p;
            LDS_V2U64(d01, d2p, curDiff + l * 16);
            unsigned d2u, dpad;
            UNPACK2(d2u, dpad, d2p);
            const float d2 = __uint_as_float(d2u);
            if (l & 1) { FMA2(aB, ww01[l], d01); cB = fmaf(w2[l], d2, cB); }
            else       { FMA2(aA, ww01[l], d01); cA = fmaf(w2[l], d2, cA); }
        }
        unsigned long long a01;
        ADD2(a01, aA, aB);
        unsigned u0u, u1u;
        UNPACK2(u0u, u1u, a01);
        const float u0 = __uint_as_float(u0u);
        const float u1 = __uint_as_float(u1u);
        const float u2 = cA + cB;

        if (active) {
            op[ 0] = s00 ? u0 : (s01 ? u1 : u2);
            op[32] = s10 ? u0 : (s11 ? u1 : u2);
            op[64] = s20 ? u0 : (s21 ? u1 : u2);
        }
        op += ostride;
        curDiff += 224u;   // 56 floats per batch
    }
}

__global__ __launch_bounds__(256) void posmix_kernel(
    const float* __restrict__ pos_atm, const float* __restrict__ pos_amn,
    const float* __restrict__ W_amn,  const float* __restrict__ W_atm,
    const int* __restrict__ seq,
    int B, int nres, int atoms, int totrows, float* __restrict__ out)
{
    __shared__ float sdif[4 * B_MAX * 56];    // 14336 B: (slot, b, l, 4)
    __shared__ float swt[4 * DV * LMAXC];     // 13312 B: (slot, ch, l)

    const int tid  = threadIdx.x;
    const int slot = tid >> 6;
    const int v    = tid & 63;
    const int row  = blockIdx.x * 4 + slot;
    const bool active = (row < totrows);
    const int rowc = active ? row : (totrows - 1);

    // binary search: largest i with g_rowstart[i] <= rowc (warp-uniform)
    int lo = 0, hi = nres - 1;
    while (lo < hi) {
        const int mid = (lo + hi + 1) >> 1;
        if (g_rowstart[mid] <= rowc) lo = mid; else hi = mid - 1;
    }
    const int i     = lo;
    const int m     = rowc - g_rowstart[i];
    const int start = g_starts[i];
    const int t     = seq[i];
    const int L     = c_res_len[t];
    const bool is_amn = (m == L);

    // --- diffs for this slot's residue, all batches, into smem ---
    if (v < 3 * L) {
        const int l = v / 3;
        const int d = v - 3 * l;
        const float* paP = pos_atm + (size_t)start * 3 + v;
        const float* pnP = pos_amn + (size_t)i * 3 + d;
        float* sd = sdif + slot * (B_MAX * 56) + l * 4 + d;
        const long astr = (long)atoms * 3;
        const long nstr = (long)nres * 3;
#pragma unroll 4
        for (int b = 0; b < B; ++b)
            sd[b * 56] = paP[b * astr] - pnP[b * nstr];
    }

    // --- stage this slot's full weight block [64][13] (dense, coalesced) ---
    {
        const float* src = is_amn
            ? (W_amn + (size_t)t * (DV * LMAXC))
            : (W_atm + ((size_t)t * LMAXC + m) * (DV * LMAXC));
        float* dst = swt + slot * (DV * LMAXC);
#pragma unroll
        for (int j = 0; j < DV * LMAXC; j += 64) dst[j + v] = src[j + v];
    }

    // --- per-thread position mapping (dense stores) ---
    const int wis = v >> 5;        // warp within slot
    const int lam = v & 31;        // lane
    int ch_c[3];
#pragma unroll
    for (int k = 0; k < 3; ++k) {
        const int P = 96 * wis + 32 * k + lam;
        ch_c[P % 3] = P / 3;
    }
    const int r3  = lam % 3;          // comp of store slot k=0
    const int ck0 = r3;
    const int ck1 = (r3 + 2) % 3;
    const int ck2 = (r3 + 1) % 3;

    // output base (float index): row segment = 192 floats
    size_t base; long ostride;
    if (is_amn) {
        base    = (size_t)B * atoms * 192 + (size_t)i * 192;
        ostride = (long)nres * 192;
    } else {
        base    = (size_t)(start + m) * 192;
        ostride = (long)atoms * 192;
    }
    float* op = out + base + 96 * wis + lam;

    __syncthreads();

    const unsigned curDiff = smem_u32(sdif) + (unsigned)(slot * (B_MAX * 56)) * 4u;
    const float* swRow = swt + slot * (DV * LMAXC);

    switch (L) {
        case  3: batch_loop< 3>(B, active, curDiff, swRow, ch_c[0], ch_c[1], ch_c[2], ck0, ck1, ck2, op, ostride); break;
        case  4: batch_loop< 4>(B, active, curDiff, swRow, ch_c[0], ch_c[1], ch_c[2], ck0, ck1, ck2, op, ostride); break;
        case  5: batch_loop< 5>(B, active, curDiff, swRow, ch_c[0], ch_c[1], ch_c[2], ck0, ck1, ck2, op, ostride); break;
        case  6: batch_loop< 6>(B, active, curDiff, swRow, ch_c[0], ch_c[1], ch_c[2], ck0, ck1, ck2, op, ostride); break;
        case  7: batch_loop< 7>(B, active, curDiff, swRow, ch_c[0], ch_c[1], ch_c[2], ck0, ck1, ck2, op, ostride); break;
        case  8: batch_loop< 8>(B, active, curDiff, swRow, ch_c[0], ch_c[1], ch_c[2], ck0, ck1, ck2, op, ostride); break;
        case  9: batch_loop< 9>(B, active, curDiff, swRow, ch_c[0], ch_c[1], ch_c[2], ck0, ck1, ck2, op, ostride); break;
        case 10: batch_loop<10>(B, active, curDiff, swRow, ch_c[0], ch_c[1], ch_c[2], ck0, ck1, ck2, op, ostride); break;
        case 11: batch_loop<11>(B, active, curDiff, swRow, ch_c[0], ch_c[1], ch_c[2], ck0, ck1, ck2, op, ostride); break;
        default: batch_loop<13>(B, active, curDiff, swRow, ch_c[0], ch_c[1], ch_c[2], ck0, ck1, ck2, op, ostride); break;
    }
}

// ---------------------------------------------------------------------------
extern "C" void kernel_launch(void* const* d_in, const int* in_sizes, int n_in,
                              void* d_out, int out_size) {
    const float* pos_atm = (const float*)d_in[0];
    const float* pos_amn = (const float*)d_in[1];
    const float* W_amn   = (const float*)d_in[2];
    const float* W_atm   = (const float*)d_in[3];
    const int*   seq     = (const int*)d_in[4];

    const int nres  = in_sizes[4];
    const int B     = in_sizes[1] / (nres * 3);
    const int atoms = in_sizes[0] / (B * 3);
    const int totrows = atoms + nres;   // sum over residues of (L+1)

    setup_kernel<<<1, 1024>>>(seq, nres);
    const int nblocks = (totrows + 3) / 4;
    posmix_kernel<<<nblocks, 256>>>(pos_atm, pos_amn, W_amn, W_atm, seq,
                                    B, nres, atoms, totrows, (float*)d_out);
}

// round 8
// speedup vs baseline: 1.2680x; 1.2680x over previous
#include <cuda_runtime.h>

#define NTYPES 20
#define LMAXC  13
#define DV     64
#define NRES_MAX 2048
#define B_MAX    16

__constant__ int c_res_len[NTYPES] = {3,4,5,5,6,6,6,7,7,7,7,7,8,8,8,9,10,10,11,13};

__device__ int g_starts[NRES_MAX];     // atom start per residue
__device__ int g_rowstart[NRES_MAX];   // first output-row per residue

// ---------------------------------------------------------------------------
// Setup: two warp-shuffle scans only (measured ~3 us).
// ---------------------------------------------------------------------------
__device__ __forceinline__ int block_excl_scan_pair(int my, int tid, int* wsum) {
    const int lane = tid & 31, wid = tid >> 5;
    int s = my;
#pragma unroll
    for (int o = 1; o < 32; o <<= 1) {
        int n = __shfl_up_sync(~0u, s, o);
        if (lane >= o) s += n;
    }
    if (lane == 31) wsum[wid] = s;
    __syncthreads();
    if (wid == 0) {
        int t = wsum[lane];
#pragma unroll
        for (int o = 1; o < 32; o <<= 1) {
            int n = __shfl_up_sync(~0u, t, o);
            if (lane >= o) t += n;
        }
        wsum[lane] = t;
    }
    __syncthreads();
    int base = ((wid > 0) ? wsum[wid - 1] : 0) + (s - my);
    __syncthreads();
    return base;
}

__global__ void setup_kernel(const int* __restrict__ seq, int nres) {
    __shared__ int wsum[32];
    __shared__ int slen[NTYPES];
    const int tid = threadIdx.x;
    if (tid < NTYPES) slen[tid] = c_res_len[tid];
    __syncthreads();

    const int j0 = 2 * tid, j1 = 2 * tid + 1;
    const int l0 = (j0 < nres) ? slen[seq[j0]] : 0;
    const int l1 = (j1 < nres) ? slen[seq[j1]] : 0;

    const int base = block_excl_scan_pair(l0 + l1, tid, wsum);
    if (j0 < nres) g_starts[j0] = base;
    if (j1 < nres) g_starts[j1] = base + l0;

    const int r0 = (j0 < nres) ? l0 + 1 : 0;
    const int r1 = (j1 < nres) ? l1 + 1 : 0;
    const int rbase = block_excl_scan_pair(r0 + r1, tid, wsum);
    if (j0 < nres) g_rowstart[j0] = rbase;
    if (j1 < nres) g_rowstart[j1] = rbase + r0;
}

// ---------------------------------------------------------------------------
// Main kernel helpers (R5 hot loop, verbatim)
// ---------------------------------------------------------------------------
#define PACK_DUP(dst, w) \
    asm("mov.b64 %0, {%1, %2};" : "=l"(dst) : "r"(__float_as_uint(w)), "r"(__float_as_uint(w)))
#define FMA2(acc, x, y) \
    asm("fma.rn.f32x2 %0, %1, %2, %3;" : "=l"(acc) : "l"(x), "l"(y), "l"(acc))
#define ADD2(dst, x, y) \
    asm("add.rn.f32x2 %0, %1, %2;" : "=l"(dst) : "l"(x), "l"(y))
#define UNPACK2(lo, hi, src) \
    asm("mov.b64 {%0, %1}, %2;" : "=r"(lo), "=r"(hi) : "l"(src))
#define LDS_V2U64(x, y, addr) \
    asm volatile("ld.shared.v2.u64 {%0, %1}, [%2];" : "=l"(x), "=l"(y) : "r"(addr))

__device__ __forceinline__ unsigned smem_u32(const void* p) {
    unsigned r;
    asm("{ .reg .u64 t; cvta.to.shared.u64 t, %1; cvt.u32.u64 %0, t; }" : "=r"(r) : "l"(p));
    return r;
}

template <int L>
__device__ __forceinline__ void batch_loop(
    int B, bool active, unsigned cur,
    const float* __restrict__ wr, float* op, long ostride)
{
    unsigned long long ww[L];
#pragma unroll
    for (int l = 0; l < L; ++l) {
        const float w = __ldg(wr + l);
        PACK_DUP(ww[l], w);
    }

#pragma unroll 2
    for (int b = 0; b < B; ++b) {
        unsigned long long aA = 0ull, aB = 0ull, cA = 0ull, cB = 0ull;
#pragma unroll
        for (int l = 0; l < L; ++l) {
            unsigned long long d01, d2p;
            LDS_V2U64(d01, d2p, cur + l * 16);
            if (l & 1) { FMA2(aB, ww[l], d01); FMA2(cB, ww[l], d2p); }
            else       { FMA2(aA, ww[l], d01); FMA2(cA, ww[l], d2p); }
        }
        unsigned long long a01, a2p;
        ADD2(a01, aA, aB);
        ADD2(a2p, cA, cB);
        if (active) {
            unsigned lo, hi, lo2, hi2;
            UNPACK2(lo, hi, a01);
            UNPACK2(lo2, hi2, a2p);
            op[0] = __uint_as_float(lo);
            op[1] = __uint_as_float(hi);
            op[2] = __uint_as_float(lo2);
        }
        op += ostride;
        cur += 224u;   // 56 floats per batch
    }
}

__global__ __launch_bounds__(256) void posmix_kernel(
    const float* __restrict__ pos_atm, const float* __restrict__ pos_amn,
    const float* __restrict__ W_amn,  const float* __restrict__ W_atm,
    const int* __restrict__ seq,
    int B, int nres, int atoms, int totrows, float* __restrict__ out)
{
    __shared__ float sdif[4 * B_MAX * 56];   // 14336 B: (slot, b, l, 4)

    const int tid  = threadIdx.x;
    const int slot = tid >> 6;
    const int v    = tid & 63;
    const int row  = blockIdx.x * 4 + slot;
    const bool active = (row < totrows);
    const int rowc = active ? row : (totrows - 1);

    // binary search: largest i with g_rowstart[i] <= rowc (warp-uniform)
    int lo = 0, hi = nres - 1;
    while (lo < hi) {
        const int mid = (lo + hi + 1) >> 1;
        if (g_rowstart[mid] <= rowc) lo = mid; else hi = mid - 1;
    }
    const int i     = lo;
    const int m     = rowc - g_rowstart[i];
    const int start = g_starts[i];
    const int t     = seq[i];
    const int L     = c_res_len[t];
    const bool is_amn = (m == L);

    // --- compute diffs for this slot's residue, all batches, into smem ---
    if (v < 3 * L) {
        const int l = v / 3;
        const int d = v - 3 * l;
        const float* paP = pos_atm + (size_t)start * 3 + v;
        const float* pnP = pos_amn + (size_t)i * 3 + d;
        float* sd = sdif + slot * (B_MAX * 56) + l * 4 + d;
        const long astr = (long)atoms * 3;
        const long nstr = (long)nres * 3;
#pragma unroll 4
        for (int b = 0; b < B; ++b)
            sd[b * 56] = paP[b * astr] - pnP[b * nstr];
    }

    // weight row for this (m, v)
    const float* wr = is_amn
        ? (W_amn + ((size_t)t * DV + v) * LMAXC)
        : (W_atm + (((size_t)t * LMAXC + m) * DV + v) * LMAXC);

    size_t base; long ostride;
    if (is_amn) {
        base    = (size_t)B * atoms * 192 + ((size_t)i * DV + v) * 3;
        ostride = (long)nres * 192;
    } else {
        base    = ((size_t)(start + m) * DV + v) * 3;
        ostride = (long)atoms * 192;
    }
    float* op = out + base;

    __syncthreads();

    const unsigned cur = smem_u32(sdif) + (unsigned)(slot * (B_MAX * 56)) * 4u;

    switch (L) {
        case  3: batch_loop< 3>(B, active, cur, wr, op, ostride); break;
        case  4: batch_loop< 4>(B, active, cur, wr, op, ostride); break;
        case  5: batch_loop< 5>(B, active, cur, wr, op, ostride); break;
        case  6: batch_loop< 6>(B, active, cur, wr, op, ostride); break;
        case  7: batch_loop< 7>(B, active, cur, wr, op, ostride); break;
        case  8: batch_loop< 8>(B, active, cur, wr, op, ostride); break;
        case  9: batch_loop< 9>(B, active, cur, wr, op, ostride); break;
        case 10: batch_loop<10>(B, active, cur, wr, op, ostride); break;
        case 11: batch_loop<11>(B, active, cur, wr, op, ostride); break;
        default: batch_loop<13>(B, active, cur, wr, op, ostride); break;
    }
}

// ---------------------------------------------------------------------------
extern "C" void kernel_launch(void* const* d_in, const int* in_sizes, int n_in,
                              void* d_out, int out_size) {
    const float* pos_atm = (const float*)d_in[0];
    const float* pos_amn = (const float*)d_in[1];
    const float* W_amn   = (const float*)d_in[2];
    const float* W_atm   = (const float*)d_in[3];
    const int*   seq     = (const int*)d_in[4];

    const int nres  = in_sizes[4];
    const int B     = in_sizes[1] / (nres * 3);
    const int atoms = in_sizes[0] / (B * 3);
    const int totrows = atoms + nres;   // sum over residues of (L+1)

    setup_kernel<<<1, 1024>>>(seq, nres);
    const int nblocks = (totrows + 3) / 4;
    posmix_kernel<<<nblocks, 256>>>(pos_atm, pos_amn, W_amn, W_atm, seq,
                                    B, nres, atoms, totrows, (float*)d_out);
}

// round 13
// speedup vs baseline: 1.3318x; 1.0503x over previous
#include <cuda_runtime.h>

#define NTYPES 20
#define LMAXC  13
#define DV     64
#define NRES_MAX 2048
#define B_MAX    16

__constant__ int c_res_len[NTYPES] = {3,4,5,5,6,6,6,7,7,7,7,7,8,8,8,9,10,10,11,13};

__device__ int g_starts[NRES_MAX];     // atom start per residue
__device__ int g_rowstart[NRES_MAX];   // first output-row per residue
// packed: i (bits 0..10) | m (bits 11..14) | start (bits 15..28)
__device__ int g_rowmap[NRES_MAX * (LMAXC + 1)];

// ---------------------------------------------------------------------------
// Setup: two warp-shuffle scans only (~3 us).
// ---------------------------------------------------------------------------
__device__ __forceinline__ int block_excl_scan_pair(int my, int tid, int* wsum) {
    const int lane = tid & 31, wid = tid >> 5;
    int s = my;
#pragma unroll
    for (int o = 1; o < 32; o <<= 1) {
        int n = __shfl_up_sync(~0u, s, o);
        if (lane >= o) s += n;
    }
    if (lane == 31) wsum[wid] = s;
    __syncthreads();
    if (wid == 0) {
        int t = wsum[lane];
#pragma unroll
        for (int o = 1; o < 32; o <<= 1) {
            int n = __shfl_up_sync(~0u, t, o);
            if (lane >= o) t += n;
        }
        wsum[lane] = t;
    }
    __syncthreads();
    int base = ((wid > 0) ? wsum[wid - 1] : 0) + (s - my);
    __syncthreads();
    return base;
}

__global__ void setup_kernel(const int* __restrict__ seq, int nres) {
    __shared__ int wsum[32];
    __shared__ int slen[NTYPES];
    const int tid = threadIdx.x;
    if (tid < NTYPES) slen[tid] = c_res_len[tid];
    __syncthreads();

    const int j0 = 2 * tid, j1 = 2 * tid + 1;
    const int l0 = (j0 < nres) ? slen[seq[j0]] : 0;
    const int l1 = (j1 < nres) ? slen[seq[j1]] : 0;

    const int base = block_excl_scan_pair(l0 + l1, tid, wsum);
    if (j0 < nres) g_starts[j0] = base;
    if (j1 < nres) g_starts[j1] = base + l0;

    const int r0 = (j0 < nres) ? l0 + 1 : 0;
    const int r1 = (j1 < nres) ? l1 + 1 : 0;
    const int rbase = block_excl_scan_pair(r0 + r1, tid, wsum);
    if (j0 < nres) g_rowstart[j0] = rbase;
    if (j1 < nres) g_rowstart[j1] = rbase + r0;
}

// ---------------------------------------------------------------------------
// Rowmap fill: one thread per residue, multi-block (parallel, ~2 us).
// ---------------------------------------------------------------------------
__global__ void fill_rowmap(const int* __restrict__ seq, int nres) {
    const int i = blockIdx.x * 256 + threadIdx.x;
    if (i >= nres) return;
    const int L = c_res_len[seq[i]];
    const int rs = g_rowstart[i];
    const int rec = i | (g_starts[i] << 15);
#pragma unroll 4
    for (int m = 0; m <= L; ++m) g_rowmap[rs + m] = rec | (m << 11);
}

// ---------------------------------------------------------------------------
// Main kernel (R5 hot loop, verbatim; single rowmap-load prologue)
// ---------------------------------------------------------------------------
#define PACK_DUP(dst, w) \
    asm("mov.b64 %0, {%1, %2};" : "=l"(dst) : "r"(__float_as_uint(w)), "r"(__float_as_uint(w)))
#define FMA2(acc, x, y) \
    asm("fma.rn.f32x2 %0, %1, %2, %3;" : "=l"(acc) : "l"(x), "l"(y), "l"(acc))
#define ADD2(dst, x, y) \
    asm("add.rn.f32x2 %0, %1, %2;" : "=l"(dst) : "l"(x), "l"(y))
#define UNPACK2(lo, hi, src) \
    asm("mov.b64 {%0, %1}, %2;" : "=r"(lo), "=r"(hi) : "l"(src))
#define LDS_V2U64(x, y, addr) \
    asm volatile("ld.shared.v2.u64 {%0, %1}, [%2];" : "=l"(x), "=l"(y) : "r"(addr))

__device__ __forceinline__ unsigned smem_u32(const void* p) {
    unsigned r;
    asm("{ .reg .u64 t; cvta.to.shared.u64 t, %1; cvt.u32.u64 %0, t; }" : "=r"(r) : "l"(p));
    return r;
}

template <int L>
__device__ __forceinline__ void batch_loop(
    int B, bool active, unsigned cur,
    const float* __restrict__ wr, float* op, long ostride)
{
    unsigned long long ww[L];
#pragma unroll
    for (int l = 0; l < L; ++l) {
        const float w = __ldg(wr + l);
        PACK_DUP(ww[l], w);
    }

#pragma unroll 2
    for (int b = 0; b < B; ++b) {
        unsigned long long aA = 0ull, aB = 0ull, cA = 0ull, cB = 0ull;
#pragma unroll
        for (int l = 0; l < L; ++l) {
            unsigned long long d01, d2p;
            LDS_V2U64(d01, d2p, cur + l * 16);
            if (l & 1) { FMA2(aB, ww[l], d01); FMA2(cB, ww[l], d2p); }
            else       { FMA2(aA, ww[l], d01); FMA2(cA, ww[l], d2p); }
        }
        unsigned long long a01, a2p;
        ADD2(a01, aA, aB);
        ADD2(a2p, cA, cB);
        if (active) {
            unsigned lo, hi, lo2, hi2;
            UNPACK2(lo, hi, a01);
            UNPACK2(lo2, hi2, a2p);
            op[0] = __uint_as_float(lo);
            op[1] = __uint_as_float(hi);
            op[2] = __uint_as_float(lo2);
        }
        op += ostride;
        cur += 224u;   // 56 floats per batch
    }
}

__global__ __launch_bounds__(256) void posmix_kernel(
    const float* __restrict__ pos_atm, const float* __restrict__ pos_amn,
    const float* __restrict__ W_amn,  const float* __restrict__ W_atm,
    const int* __restrict__ seq,
    int B, int nres, int atoms, int totrows, float* __restrict__ out)
{
    __shared__ float sdif[4 * B_MAX * 56];   // 14336 B: (slot, b, l, 4)

    const int tid  = threadIdx.x;
    const int slot = tid >> 6;
    const int v    = tid & 63;
    const int row  = blockIdx.x * 4 + slot;
    const bool active = (row < totrows);
    const int rowc = active ? row : (totrows - 1);

    const int rm    = g_rowmap[rowc];          // warp-uniform single load
    const int i     = rm & 2047;
    const int m     = (rm >> 11) & 15;
    const int start = rm >> 15;
    const int t     = seq[i];
    const int L     = c_res_len[t];
    const bool is_amn = (m == L);

    // --- compute diffs for this slot's residue, all batches, into smem ---
    if (v < 3 * L) {
        const int l = v / 3;
        const int d = v - 3 * l;
        const float* paP = pos_atm + (size_t)start * 3 + v;
        const float* pnP = pos_amn + (size_t)i * 3 + d;
        float* sd = sdif + slot * (B_MAX * 56) + l * 4 + d;
        const long astr = (long)atoms * 3;
        const long nstr = (long)nres * 3;
#pragma unroll 4
        for (int b = 0; b < B; ++b)
            sd[b * 56] = paP[b * astr] - pnP[b * nstr];
    }

    // weight row for this (m, v)
    const float* wr = is_amn
        ? (W_amn + ((size_t)t * DV + v) * LMAXC)
        : (W_atm + (((size_t)t * LMAXC + m) * DV + v) * LMAXC);

    size_t base; long ostride;
    if (is_amn) {
        base    = (size_t)B * atoms * 192 + ((size_t)i * DV + v) * 3;
        ostride = (long)nres * 192;
    } else {
        base    = ((size_t)(start + m) * DV + v) * 3;
        ostride = (long)atoms * 192;
    }
    float* op = out + base;

    __syncthreads();

    const unsigned cur = smem_u32(sdif) + (unsigned)(slot * (B_MAX * 56)) * 4u;

    switch (L) {
        case  3: batch_loop< 3>(B, active, cur, wr, op, ostride); break;
        case  4: batch_loop< 4>(B, active, cur, wr, op, ostride); break;
        case  5: batch_loop< 5>(B, active, cur, wr, op, ostride); break;
        case  6: batch_loop< 6>(B, active, cur, wr, op, ostride); break;
        case  7: batch_loop< 7>(B, active, cur, wr, op, ostride); break;
        case  8: batch_loop< 8>(B, active, cur, wr, op, ostride); break;
        case  9: batch_loop< 9>(B, active, cur, wr, op, ostride); break;
        case 10: batch_loop<10>(B, active, cur, wr, op, ostride); break;
        case 11: batch_loop<11>(B, active, cur, wr, op, ostride); break;
        default: batch_loop<13>(B, active, cur, wr, op, ostride); break;
    }
}

// ---------------------------------------------------------------------------
extern "C" void kernel_launch(void* const* d_in, const int* in_sizes, int n_in,
                              void* d_out, int out_size) {
    const float* pos_atm = (const float*)d_in[0];
    const float* pos_amn = (const float*)d_in[1];
    const float* W_amn   = (const float*)d_in[2];
    const float* W_atm   = (const float*)d_in[3];
    const int*   seq     = (const int*)d_in[4];

    const int nres  = in_sizes[4];
    const int B     = in_sizes[1] / (nres * 3);
    const int atoms = in_sizes[0] / (B * 3);
    const int totrows = atoms + nres;   // sum over residues of (L+1)

    setup_kernel<<<1, 1024>>>(seq, nres);
    fill_rowmap<<<(nres + 255) / 256, 256>>>(seq, nres);
    const int nblocks = (totrows + 3) / 4;
    posmix_kernel<<<nblocks, 256>>>(pos_atm, pos_amn, W_amn, W_atm, seq,
                                    B, nres, atoms, totrows, (float*)d_out);
}